// round 2
// baseline (speedup 1.0000x reference)
#include <cuda_runtime.h>
#include <math.h>

// Problem constants
#define NSENT 4096      // N sentences
#define MKNOW 4096      // M knowledge rows
#define HEADS 8
#define SENTD 1024      // sent_dim
#define HD    128       // per-head hidden dim

// Scratch (static device arrays: allocation-free per harness rules)
__device__ float g_S[(size_t)HEADS * NSENT * HD];        // 16 MB  S[h][n][e]
__device__ float g_Kt[(size_t)HEADS * HD * MKNOW];       // 16 MB  Kt[h][e][m]
__device__ float g_colsum[HEADS * MKNOW];                // 128 KB sum_n exp(score[h,n,m])
__device__ float g_concat[(size_t)NSENT * (HEADS * SENTD)]; // 128 MB concat[n][h*1024+d]

__global__ void zero_colsum_k() {
    int i = blockIdx.x * blockDim.x + threadIdx.x;
    if (i < HEADS * MKNOW) g_colsum[i] = 0.0f;
}

enum { MODE_PLAIN = 0, MODE_BIAS = 1, MODE_TRANS_BIAS = 2, MODE_EXP = 3 };

// Classic 128x128x8 fp32 SGEMM, 256 threads, 8x8 micro-tile, register prefetch.
// All dims used here are divisible by tile sizes, so no bounds checks.
// MODE_EXP: C = exp(alpha*acc), plus per-column sums accumulated into colsum.
// MODE_TRANS_BIAS: writes C transposed (C[col*ldc + row]) with bias per col.
template <int MODE>
__global__ void __launch_bounds__(256)
sgemm_k(const float* __restrict__ A, const float* __restrict__ B,
        float* __restrict__ C,
        int Kn, int lda, int ldb, int ldc,
        long long sA, long long sB, long long sC,
        const float* __restrict__ bias, int sBias,
        float alpha, float* __restrict__ colsum, int sCol)
{
    __shared__ float sm[2048];        // As[8][128] (k-major) + Bs[8][128]
    float* As = sm;
    float* Bs = sm + 1024;

    const int h = blockIdx.z;
    A += (long long)h * sA;
    B += (long long)h * sB;
    C += (long long)h * sC;

    const int t    = threadIdx.x;
    const int row0 = blockIdx.y * 128;
    const int col0 = blockIdx.x * 128;

    // load mapping: A tile 128x8 -> 1 float4/thread, B tile 8x128 -> 1 float4/thread
    const int a_row = t >> 1;
    const int a_k4  = (t & 1) << 2;
    const int b_k   = t >> 5;
    const int b_col = (t & 31) << 2;

    const float* Ap = A + (long long)(row0 + a_row) * lda + a_k4;
    const float* Bp = B + (long long)b_k * ldb + col0 + b_col;

    const int ty = t >> 4;   // row group 0..15
    const int tx = t & 15;   // col group 0..15

    float acc[8][8];
#pragma unroll
    for (int i = 0; i < 8; i++)
#pragma unroll
        for (int j = 0; j < 8; j++) acc[i][j] = 0.0f;

    float4 av = *(const float4*)Ap;
    float4 bv = *(const float4*)Bp;

    for (int k0 = 0; k0 < Kn; k0 += 8) {
        // stage current tile into smem
        As[(a_k4 + 0) * 128 + a_row] = av.x;
        As[(a_k4 + 1) * 128 + a_row] = av.y;
        As[(a_k4 + 2) * 128 + a_row] = av.z;
        As[(a_k4 + 3) * 128 + a_row] = av.w;
        *(float4*)&Bs[b_k * 128 + b_col] = bv;
        __syncthreads();

        // prefetch next tile (overlaps with compute below)
        if (k0 + 8 < Kn) {
            Ap += 8;
            Bp += (long long)8 * ldb;
            av = *(const float4*)Ap;
            bv = *(const float4*)Bp;
        }

        float ar[8], br[8];
#pragma unroll
        for (int kk = 0; kk < 8; kk++) {
#pragma unroll
            for (int i = 0; i < 8; i++) ar[i] = As[kk * 128 + ty * 8 + i];
#pragma unroll
            for (int j = 0; j < 8; j++) br[j] = Bs[kk * 128 + tx * 8 + j];
#pragma unroll
            for (int i = 0; i < 8; i++)
#pragma unroll
                for (int j = 0; j < 8; j++) acc[i][j] += ar[i] * br[j];
        }
        __syncthreads();
    }

    const int gr = row0 + ty * 8;
    const int gc = col0 + tx * 8;

    if (MODE == MODE_PLAIN || MODE == MODE_BIAS) {
        float bvs[8];
#pragma unroll
        for (int j = 0; j < 8; j++)
            bvs[j] = (MODE == MODE_BIAS) ? bias[(long long)h * sBias + gc + j] : 0.0f;
#pragma unroll
        for (int i = 0; i < 8; i++) {
            float4 v0 = make_float4(acc[i][0] + bvs[0], acc[i][1] + bvs[1],
                                    acc[i][2] + bvs[2], acc[i][3] + bvs[3]);
            float4 v1 = make_float4(acc[i][4] + bvs[4], acc[i][5] + bvs[5],
                                    acc[i][6] + bvs[6], acc[i][7] + bvs[7]);
            *(float4*)&C[(long long)(gr + i) * ldc + gc]     = v0;
            *(float4*)&C[(long long)(gr + i) * ldc + gc + 4] = v1;
        }
    } else if (MODE == MODE_TRANS_BIAS) {
        // C[col][row] layout, ldc = number of rows
#pragma unroll
        for (int j = 0; j < 8; j++) {
            float b = bias[(long long)h * sBias + gc + j];
            float4 v0 = make_float4(acc[0][j] + b, acc[1][j] + b,
                                    acc[2][j] + b, acc[3][j] + b);
            float4 v1 = make_float4(acc[4][j] + b, acc[5][j] + b,
                                    acc[6][j] + b, acc[7][j] + b);
            *(float4*)&C[(long long)(gc + j) * ldc + gr]     = v0;
            *(float4*)&C[(long long)(gc + j) * ldc + gr + 4] = v1;
        }
    } else { // MODE_EXP
        float psum[8];
#pragma unroll
        for (int j = 0; j < 8; j++) psum[j] = 0.0f;
#pragma unroll
        for (int i = 0; i < 8; i++) {
            float v[8];
#pragma unroll
            for (int j = 0; j < 8; j++) {
                v[j] = expf(acc[i][j] * alpha);
                psum[j] += v[j];
            }
            *(float4*)&C[(long long)(gr + i) * ldc + gc]     = make_float4(v[0], v[1], v[2], v[3]);
            *(float4*)&C[(long long)(gr + i) * ldc + gc + 4] = make_float4(v[4], v[5], v[6], v[7]);
        }
        // reduce 16 row-groups -> 128 column sums, one atomicAdd per column
        // (safe to reuse sm: everyone passed the final loop __syncthreads and
        //  nobody reads As/Bs afterwards)
        float* red = sm; // 16 x 128
#pragma unroll
        for (int j = 0; j < 8; j++) red[ty * 128 + tx * 8 + j] = psum[j];
        __syncthreads();
        if (t < 128) {
            float s = 0.0f;
#pragma unroll
            for (int g = 0; g < 16; g++) s += red[g * 128 + t];
            atomicAdd(&colsum[(long long)h * sCol + col0 + t], s);
        }
    }
}

// weights[h,n,m] /= colsum[h,m]  (vectorized, N*M = 2^24 so h = e>>24)
__global__ void normalize_k(float* __restrict__ w) {
    const long long total4 = (long long)HEADS * NSENT * MKNOW / 4;
    for (long long i = (long long)blockIdx.x * blockDim.x + threadIdx.x;
         i < total4; i += (long long)gridDim.x * blockDim.x) {
        long long e = i << 2;
        int h = (int)(e >> 24);
        int m = (int)(e & (MKNOW - 1));
        const float* cs = &g_colsum[h * MKNOW + m];
        float4 v = ((float4*)w)[i];
        v.x /= cs[0];
        v.y /= cs[1];
        v.z /= cs[2];
        v.w /= cs[3];
        ((float4*)w)[i] = v;
    }
}

extern "C" void kernel_launch(void* const* d_in, const int* in_sizes, int n_in,
                              void* d_out, int out_size)
{
    const float* sentences = (const float*)d_in[0]; // [4096,1024]
    const float* knowledge = (const float*)d_in[1]; // [4096,1024]
    const float* W_s       = (const float*)d_in[2]; // [8,1024,128]
    const float* b_s       = (const float*)d_in[3]; // [8,128]
    const float* W_k       = (const float*)d_in[4]; // [8,1024,128]
    const float* b_k       = (const float*)d_in[5]; // [8,128]
    const float* W_f       = (const float*)d_in[6]; // [8192,1024]
    const float* b_f       = (const float*)d_in[7]; // [1024]

    float* out0 = (float*)d_out;                          // output [4096,1024]
    float* wout = out0 + (long long)NSENT * SENTD;        // weights_cat [8*4096, 4096]

    float* gS  = nullptr; cudaGetSymbolAddress((void**)&gS,  g_S);
    float* gKt = nullptr; cudaGetSymbolAddress((void**)&gKt, g_Kt);
    float* gCs = nullptr; cudaGetSymbolAddress((void**)&gCs, g_colsum);
    float* gCc = nullptr; cudaGetSymbolAddress((void**)&gCc, g_concat);

    const float inv_sqrt_hd = 0.08838834764831845f; // 1/sqrt(128)

    zero_colsum_k<<<(HEADS * MKNOW + 255) / 256, 256>>>();

    // S[h] = sentences @ W_s[h] + b_s[h]        -> g_S [h][n][e]
    sgemm_k<MODE_BIAS><<<dim3(1, NSENT / 128, HEADS), 256>>>(
        sentences, W_s, gS,
        SENTD, SENTD, HD, HD,
        0LL, (long long)SENTD * HD, (long long)NSENT * HD,
        b_s, HD, 1.0f, nullptr, 0);

    // K[h] = knowledge @ W_k[h] + b_k[h], stored transposed -> g_Kt [h][e][m]
    sgemm_k<MODE_TRANS_BIAS><<<dim3(1, MKNOW / 128, HEADS), 256>>>(
        knowledge, W_k, gKt,
        SENTD, SENTD, HD, MKNOW,
        0LL, (long long)SENTD * HD, (long long)HD * MKNOW,
        b_k, HD, 1.0f, nullptr, 0);

    // exp(scores[h]) = exp( S[h] @ Kt[h] / sqrt(HD) ) -> weights output region;
    // accumulate per-(h,m) column sums into g_colsum
    sgemm_k<MODE_EXP><<<dim3(MKNOW / 128, NSENT / 128, HEADS), 256>>>(
        gS, gKt, wout,
        HD, HD, MKNOW, MKNOW,
        (long long)NSENT * HD, (long long)HD * MKNOW, (long long)NSENT * MKNOW,
        nullptr, 0, inv_sqrt_hd, gCs, MKNOW);

    // weights /= colsum  (softmax over sentences)
    normalize_k<<<4096, 256>>>(wout);

    // attn_out[h] = weights[h] @ knowledge -> concat[n][h*1024 + d]
    sgemm_k<MODE_PLAIN><<<dim3(SENTD / 128, NSENT / 128, HEADS), 256>>>(
        wout, knowledge, gCc,
        MKNOW, MKNOW, SENTD, HEADS * SENTD,
        (long long)NSENT * MKNOW, 0LL, (long long)SENTD,
        nullptr, 0, 1.0f, nullptr, 0);

    // output = concat @ W_f + b_f
    sgemm_k<MODE_BIAS><<<dim3(SENTD / 128, NSENT / 128, 1), 256>>>(
        gCc, W_f, out0,
        HEADS * SENTD, HEADS * SENTD, SENTD, SENTD,
        0LL, 0LL, 0LL,
        b_f, 0, 1.0f, nullptr, 0);
}

// round 4
// speedup vs baseline: 2.2856x; 2.2856x over previous
#include <cuda_runtime.h>
#include <cstdint>
#include <math.h>

// ---------------- problem constants ----------------
#define NSENT 4096
#define MKNOW 4096
#define HEADS 8
#define SENTD 1024
#define HD    128

// ---------------- GEMM tile config ----------------
#define BM 128
#define BN 128
#define BK 16
#define TPAD 20                               // floats per smem row (16 + 4 pad)
#define TILE_FLOATS (128 * TPAD)              // one operand tile
#define STAGE_FLOATS (2 * TILE_FLOATS)        // A + B
#define STAGES 4
#define SMEM_BYTES (STAGES * STAGE_FLOATS * 4)   // 80 KB

// ---------------- scratch (static device arrays) ----------------
__device__ float g_sent3[(size_t)NSENT*3*SENTD];
__device__ float g_know3[(size_t)MKNOW*3*SENTD];
__device__ float g_WsT3[(size_t)HEADS*HD*3*SENTD];
__device__ float g_WkT3[(size_t)HEADS*HD*3*SENTD];
__device__ float g_S  [(size_t)HEADS*NSENT*HD];
__device__ float g_Kp [(size_t)HEADS*MKNOW*HD];
__device__ float g_S3 [(size_t)HEADS*NSENT*3*HD];
__device__ float g_Kp3[(size_t)HEADS*MKNOW*3*HD];
__device__ float g_knowT[(size_t)SENTD*MKNOW];
__device__ float g_WfT[(size_t)SENTD*HEADS*SENTD];
__device__ float g_concat[(size_t)NSENT*HEADS*SENTD];
__device__ float g_colsum[HEADS*MKNOW];

// ---------------- helpers ----------------
__device__ __forceinline__ uint32_t smem_u32(const void* p) {
    uint32_t a;
    asm("{ .reg .u64 t; cvta.to.shared.u64 t, %1; cvt.u32.u64 %0, t; }" : "=r"(a) : "l"(p));
    return a;
}
__device__ __forceinline__ float tf32_hi(float x) {
    uint32_t r;
    asm("cvt.rna.tf32.f32 %0, %1;" : "=r"(r) : "f"(x));
    return __uint_as_float(r);
}

#define CP_ASYNC16(dst, src) \
    asm volatile("cp.async.cg.shared.global [%0], [%1], 16;" :: "r"(dst), "l"(src) : "memory")
#define CP_COMMIT() asm volatile("cp.async.commit_group;" ::: "memory")
#define CP_WAIT2()  asm volatile("cp.async.wait_group 2;" ::: "memory")

#define MMA_TF32(d, a, b) \
    asm volatile("mma.sync.aligned.m16n8k8.row.col.f32.tf32.tf32.f32 " \
        "{%0,%1,%2,%3}, {%4,%5,%6,%7}, {%8,%9}, {%0,%1,%2,%3};" \
        : "+f"((d)[0]), "+f"((d)[1]), "+f"((d)[2]), "+f"((d)[3]) \
        : "r"((a)[0]), "r"((a)[1]), "r"((a)[2]), "r"((a)[3]), \
          "r"((b)[0]), "r"((b)[1]))

enum { MODE_PLAIN = 0, MODE_BIAS = 1, MODE_EXP = 3 };

// ---------------- tf32 mma.sync GEMM ----------------
// C[M x N] (+ per-blockIdx.z batch strides) = A[M x K] * B[N x K]^T, fp32
// row-major, all dims divisible by tiles (M,N by 128; K by 16).
template <int MODE>
__global__ void __launch_bounds__(256)
tgemm_k(const float* __restrict__ A, const float* __restrict__ B, float* __restrict__ C,
        int Kn, int lda, int ldb, int ldc,
        long long sA, long long sB, long long sC,
        const float* __restrict__ bias, int sBias, float alpha)
{
    extern __shared__ float smem[];
    const uint32_t smem_b = smem_u32(smem);
    const int h = blockIdx.z;
    A += (long long)h * sA;
    B += (long long)h * sB;
    C += (long long)h * sC;

    const int t = threadIdx.x;
    const int wid = t >> 5, lane = t & 31;
    const int lr = lane >> 2;    // 0..7
    const int lc = lane & 3;     // 0..3
    const int wm = (wid & 1) * 64;     // warp row offset in CTA tile
    const int wn = (wid >> 1) * 32;    // warp col offset
    const int row0 = blockIdx.y * BM;
    const int col0 = blockIdx.x * BN;
    const int nKT = Kn / BK;

    // cp.async fill: A tile 128 rows x 4 chunks (16B), thread handles chunks t, t+256; B same
    const int f_row0 = t >> 2, f_cc0 = t & 3;          // chunk t
    const int f_row1 = (t + 256) >> 2, f_cc1 = f_cc0;  // chunk t+256

#define LOAD_TILE(kt, s) do { \
    long long _k0 = (long long)(kt) * BK; \
    uint32_t _sa = smem_b + (s) * STAGE_FLOATS * 4; \
    uint32_t _sb = _sa + TILE_FLOATS * 4; \
    CP_ASYNC16(_sa + (f_row0 * TPAD + f_cc0 * 4) * 4, A + (long long)(row0 + f_row0) * lda + _k0 + f_cc0 * 4); \
    CP_ASYNC16(_sa + (f_row1 * TPAD + f_cc1 * 4) * 4, A + (long long)(row0 + f_row1) * lda + _k0 + f_cc1 * 4); \
    CP_ASYNC16(_sb + (f_row0 * TPAD + f_cc0 * 4) * 4, B + (long long)(col0 + f_row0) * ldb + _k0 + f_cc0 * 4); \
    CP_ASYNC16(_sb + (f_row1 * TPAD + f_cc1 * 4) * 4, B + (long long)(col0 + f_row1) * ldb + _k0 + f_cc1 * 4); \
} while (0)

    float acc[4][4][4];
#pragma unroll
    for (int i = 0; i < 4; i++)
#pragma unroll
        for (int j = 0; j < 4; j++)
#pragma unroll
            for (int q = 0; q < 4; q++) acc[i][j][q] = 0.0f;

    // prologue: stages 0..2
    LOAD_TILE(0, 0); CP_COMMIT();
    LOAD_TILE(1, 1); CP_COMMIT();
    LOAD_TILE(2, 2); CP_COMMIT();

    for (int it = 0; it < nKT; it++) {
        CP_WAIT2();            // stage `it` landed
        __syncthreads();       // and everyone done reading stage it-1 wrap target
        if (it + 3 < nKT) LOAD_TILE(it + 3, (it + 3) & 3);
        CP_COMMIT();           // uniform group count (may be empty)

        const float* As = smem + (it & 3) * STAGE_FLOATS;
        const float* Bs = As + TILE_FLOATS;
        const float* Ab = As + (wm + lr) * TPAD + lc;
        const float* Bb = Bs + (wn + lr) * TPAD + lc;
#pragma unroll
        for (int ks = 0; ks < 2; ks++) {
            const int k0 = ks * 8;
            uint32_t a[4][4], b[4][2];
#pragma unroll
            for (int i = 0; i < 4; i++) {
                const float* p = Ab + i * 16 * TPAD + k0;
                a[i][0] = __float_as_uint(p[0]);
                a[i][1] = __float_as_uint(p[8 * TPAD]);
                a[i][2] = __float_as_uint(p[4]);
                a[i][3] = __float_as_uint(p[8 * TPAD + 4]);
            }
#pragma unroll
            for (int j = 0; j < 4; j++) {
                const float* p = Bb + j * 8 * TPAD + k0;
                b[j][0] = __float_as_uint(p[0]);
                b[j][1] = __float_as_uint(p[4]);
            }
#pragma unroll
            for (int i = 0; i < 4; i++)
#pragma unroll
                for (int j = 0; j < 4; j++)
                    MMA_TF32(acc[i][j], a[i], b[j]);
        }
    }

    // epilogue: d0,d1 -> (r, c..c+1); d2,d3 -> (r+8, c..c+1)
#pragma unroll
    for (int j = 0; j < 4; j++) {
        const int c = col0 + wn + j * 8 + lc * 2;
        float b0 = 0.0f, b1 = 0.0f;
        if (MODE == MODE_BIAS) {
            b0 = bias[(long long)h * sBias + c];
            b1 = bias[(long long)h * sBias + c + 1];
        }
#pragma unroll
        for (int i = 0; i < 4; i++) {
            const int r = row0 + wm + i * 16 + lr;
            float d0 = acc[i][j][0], d1 = acc[i][j][1];
            float d2 = acc[i][j][2], d3 = acc[i][j][3];
            if (MODE == MODE_EXP) {
                d0 = __expf(d0 * alpha); d1 = __expf(d1 * alpha);
                d2 = __expf(d2 * alpha); d3 = __expf(d3 * alpha);
            } else if (MODE == MODE_BIAS) {
                d0 += b0; d1 += b1; d2 += b0; d3 += b1;
            }
            *(float2*)&C[(long long)r * ldc + c]       = make_float2(d0, d1);
            *(float2*)&C[(long long)(r + 8) * ldc + c] = make_float2(d2, d3);
        }
    }
}

// ---------------- prep / softmax kernels ----------------

// in [R,C] -> out [R,3C]: a_style=1 -> [hi|lo|hi], a_style=0 -> [hi|hi|lo]
__global__ void split3_k(const float* __restrict__ in, float* __restrict__ out,
                         int C, long long total, int a_style) {
    for (long long i = (long long)blockIdx.x * blockDim.x + threadIdx.x;
         i < total; i += (long long)gridDim.x * blockDim.x) {
        long long r = i / C;
        int c = (int)(i - r * C);
        float x = in[i];
        float hi = tf32_hi(x), lo = x - hi;
        float* o = out + r * 3LL * C;
        o[c] = hi;
        o[C + c] = a_style ? lo : hi;
        o[2 * C + c] = a_style ? hi : lo;
    }
}

// W [h][D][E] -> out [h][E][3D] B-style ([hi|hi|lo])
__global__ void split3T_k(const float* __restrict__ in, float* __restrict__ out, int D, int E) {
    __shared__ float tile[32][33];
    const int h = blockIdx.z;
    const int e0 = blockIdx.x * 32, d0 = blockIdx.y * 32;
    in += (size_t)h * D * E;
    out += (size_t)h * E * 3 * D;
    const int x = threadIdx.x, y = threadIdx.y;
#pragma unroll
    for (int j = 0; j < 32; j += 8)
        tile[y + j][x] = in[(long long)(d0 + y + j) * E + e0 + x];
    __syncthreads();
#pragma unroll
    for (int j = 0; j < 32; j += 8) {
        float v = tile[x][y + j];
        float hi = tf32_hi(v), lo = v - hi;
        long long o = (long long)(e0 + y + j) * 3 * D + d0 + x;
        out[o] = hi;
        out[o + D] = hi;
        out[o + 2 * D] = lo;
    }
}

// in [R,C] -> out [C,R]; rnd=1 applies RNA tf32 rounding (halves mma truncation error)
__global__ void transpose_k(const float* __restrict__ in, float* __restrict__ out,
                            int R, int C, int rnd) {
    __shared__ float tile[32][33];
    const int c0 = blockIdx.x * 32, r0 = blockIdx.y * 32;
    const int x = threadIdx.x, y = threadIdx.y;
#pragma unroll
    for (int j = 0; j < 32; j += 8)
        tile[y + j][x] = in[(long long)(r0 + y + j) * C + c0 + x];
    __syncthreads();
#pragma unroll
    for (int j = 0; j < 32; j += 8) {
        float v = tile[x][y + j];
        out[(long long)(c0 + y + j) * R + r0 + x] = rnd ? tf32_hi(v) : v;
    }
}

__global__ void zero_colsum_k() {
    int i = blockIdx.x * blockDim.x + threadIdx.x;
    if (i < HEADS * MKNOW) g_colsum[i] = 0.0f;
}

// colsum[h][m] = sum_n w[h][n][m]; grid (M/256, N/256, H)
__global__ void colsum_k(const float* __restrict__ w) {
    const int m = blockIdx.x * 256 + threadIdx.x;
    const int h = blockIdx.z;
    const float* p = w + (size_t)h * NSENT * MKNOW + (size_t)blockIdx.y * 256 * MKNOW + m;
    float s = 0.0f;
#pragma unroll 4
    for (int r = 0; r < 256; r++) s += p[(long long)r * MKNOW];
    atomicAdd(&g_colsum[h * MKNOW + m], s);
}

// w[h,n,m] /= colsum[h,m]
__global__ void normalize_k(float* __restrict__ w) {
    const long long total4 = (long long)HEADS * NSENT * MKNOW / 4;
    for (long long i = (long long)blockIdx.x * blockDim.x + threadIdx.x;
         i < total4; i += (long long)gridDim.x * blockDim.x) {
        long long e = i << 2;
        int h = (int)(e >> 24);
        int m = (int)(e & (MKNOW - 1));
        const float* cs = &g_colsum[h * MKNOW + m];
        float4 v = ((float4*)w)[i];
        v.x /= cs[0]; v.y /= cs[1]; v.z /= cs[2]; v.w /= cs[3];
        ((float4*)w)[i] = v;
    }
}

// ---------------- launch ----------------
extern "C" void kernel_launch(void* const* d_in, const int* in_sizes, int n_in,
                              void* d_out, int out_size)
{
    const float* sentences = (const float*)d_in[0];
    const float* knowledge = (const float*)d_in[1];
    const float* W_s = (const float*)d_in[2];
    const float* b_s = (const float*)d_in[3];
    const float* W_k = (const float*)d_in[4];
    const float* b_k = (const float*)d_in[5];
    const float* W_f = (const float*)d_in[6];
    const float* b_f = (const float*)d_in[7];

    float* out0 = (float*)d_out;                        // [4096,1024]
    float* wout = out0 + (long long)NSENT * SENTD;      // [8*4096,4096]

    float* gSent3 = nullptr; cudaGetSymbolAddress((void**)&gSent3, g_sent3);
    float* gKnow3 = nullptr; cudaGetSymbolAddress((void**)&gKnow3, g_know3);
    float* gWsT3 = nullptr;  cudaGetSymbolAddress((void**)&gWsT3, g_WsT3);
    float* gWkT3 = nullptr;  cudaGetSymbolAddress((void**)&gWkT3, g_WkT3);
    float* gS = nullptr;     cudaGetSymbolAddress((void**)&gS, g_S);
    float* gKp = nullptr;    cudaGetSymbolAddress((void**)&gKp, g_Kp);
    float* gS3 = nullptr;    cudaGetSymbolAddress((void**)&gS3, g_S3);
    float* gKp3 = nullptr;   cudaGetSymbolAddress((void**)&gKp3, g_Kp3);
    float* gKnT = nullptr;   cudaGetSymbolAddress((void**)&gKnT, g_knowT);
    float* gWfT = nullptr;   cudaGetSymbolAddress((void**)&gWfT, g_WfT);
    float* gCc = nullptr;    cudaGetSymbolAddress((void**)&gCc, g_concat);

    cudaFuncSetAttribute(tgemm_k<MODE_PLAIN>, cudaFuncAttributeMaxDynamicSharedMemorySize, SMEM_BYTES);
    cudaFuncSetAttribute(tgemm_k<MODE_BIAS>,  cudaFuncAttributeMaxDynamicSharedMemorySize, SMEM_BYTES);
    cudaFuncSetAttribute(tgemm_k<MODE_EXP>,   cudaFuncAttributeMaxDynamicSharedMemorySize, SMEM_BYTES);

    const float inv_sqrt_hd = 0.08838834764831845f;

    // --- prep: tf32 splits + transposes ---
    split3_k<<<1024, 256>>>(sentences, gSent3, SENTD, (long long)NSENT * SENTD, 1);
    split3_k<<<1024, 256>>>(knowledge, gKnow3, SENTD, (long long)MKNOW * SENTD, 1);
    split3T_k<<<dim3(HD / 32, SENTD / 32, HEADS), dim3(32, 8)>>>(W_s, gWsT3, SENTD, HD);
    split3T_k<<<dim3(HD / 32, SENTD / 32, HEADS), dim3(32, 8)>>>(W_k, gWkT3, SENTD, HD);
    transpose_k<<<dim3(SENTD / 32, MKNOW / 32), dim3(32, 8)>>>(knowledge, gKnT, MKNOW, SENTD, 1);
    transpose_k<<<dim3(SENTD / 32, (HEADS * SENTD) / 32), dim3(32, 8)>>>(W_f, gWfT, HEADS * SENTD, SENTD, 1);
    zero_colsum_k<<<(HEADS * MKNOW + 255) / 256, 256>>>();

    // --- projections (split tf32, K=3072) ---
    tgemm_k<MODE_BIAS><<<dim3(1, NSENT / BM, HEADS), 256, SMEM_BYTES>>>(
        gSent3, gWsT3, gS, 3 * SENTD, 3 * SENTD, 3 * SENTD, HD,
        0LL, (long long)HD * 3 * SENTD, (long long)NSENT * HD, b_s, HD, 0.0f);
    tgemm_k<MODE_BIAS><<<dim3(1, MKNOW / BM, HEADS), 256, SMEM_BYTES>>>(
        gKnow3, gWkT3, gKp, 3 * SENTD, 3 * SENTD, 3 * SENTD, HD,
        0LL, (long long)HD * 3 * SENTD, (long long)MKNOW * HD, b_k, HD, 0.0f);

    // --- split S/Kp for the scores GEMM ---
    split3_k<<<1024, 256>>>(gS, gS3, HD, (long long)HEADS * NSENT * HD, 1);
    split3_k<<<1024, 256>>>(gKp, gKp3, HD, (long long)HEADS * MKNOW * HD, 0);

    // --- scores (split tf32, K=384) -> exp -> weights region of d_out ---
    tgemm_k<MODE_EXP><<<dim3(MKNOW / BN, NSENT / BM, HEADS), 256, SMEM_BYTES>>>(
        gS3, gKp3, wout, 3 * HD, 3 * HD, 3 * HD, MKNOW,
        (long long)NSENT * 3 * HD, (long long)MKNOW * 3 * HD, (long long)NSENT * MKNOW,
        nullptr, 0, inv_sqrt_hd);

    // --- softmax over sentences ---
    colsum_k<<<dim3(MKNOW / 256, NSENT / 256, HEADS), 256>>>(wout);
    normalize_k<<<4096, 256>>>(wout);

    // --- attn: weights[h] @ knowledge -> concat[n][h*1024+d] (plain tf32, K=4096) ---
    tgemm_k<MODE_PLAIN><<<dim3(SENTD / BN, NSENT / BM, HEADS), 256, SMEM_BYTES>>>(
        wout, gKnT, gCc, MKNOW, MKNOW, MKNOW, HEADS * SENTD,
        (long long)NSENT * MKNOW, 0LL, (long long)SENTD, nullptr, 0, 0.0f);

    // --- final: concat @ W_f + b_f (plain tf32, K=8192) ---
    tgemm_k<MODE_BIAS><<<dim3(SENTD / BN, NSENT / BM, 1), 256, SMEM_BYTES>>>(
        gCc, gWfT, out0, HEADS * SENTD, HEADS * SENTD, HEADS * SENTD, SENTD,
        0LL, 0LL, 0LL, b_f, 0, 0.0f);
}

// round 5
// speedup vs baseline: 2.6232x; 1.1477x over previous
#include <cuda_runtime.h>
#include <cstdint>
#include <math.h>

// ---------------- problem constants ----------------
#define NSENT 4096
#define MKNOW 4096
#define HEADS 8
#define SENTD 1024
#define HD    128

// ---------------- GEMM tile config ----------------
#define BM 128
#define BN 128
#define BK 16
#define TPAD 24                               // floats per smem row (16 + 8 pad; conflict-free LDS.64)
#define TILE_FLOATS (128 * TPAD)
#define STAGE_FLOATS (2 * TILE_FLOATS)
#define STAGES 4
#define SMEM_BYTES (STAGES * STAGE_FLOATS * 4)   // 96 KB -> 2 CTAs/SM

// ---------------- scratch (static device arrays) ----------------
__device__ float g_sent3[(size_t)NSENT*3*SENTD];
__device__ float g_know3[(size_t)MKNOW*3*SENTD];
__device__ float g_WsT3[(size_t)HEADS*HD*3*SENTD];
__device__ float g_WkT3[(size_t)HEADS*HD*3*SENTD];
__device__ float g_S  [(size_t)HEADS*NSENT*HD];
__device__ float g_Kp [(size_t)HEADS*MKNOW*HD];
__device__ float g_S3 [(size_t)HEADS*NSENT*3*HD];
__device__ float g_Kp3[(size_t)HEADS*MKNOW*3*HD];
__device__ float g_knowT[(size_t)SENTD*MKNOW];
__device__ float g_WfT[(size_t)SENTD*HEADS*SENTD];
__device__ float g_concat[(size_t)NSENT*HEADS*SENTD];
__device__ float g_wrnd[(size_t)HEADS*NSENT*MKNOW];     // rounded+permuted weights (attn A)
__device__ float g_colsum[HEADS*MKNOW];

// ---------------- helpers ----------------
__device__ __forceinline__ uint32_t smem_u32(const void* p) {
    uint32_t a;
    asm("{ .reg .u64 t; cvta.to.shared.u64 t, %1; cvt.u32.u64 %0, t; }" : "=r"(a) : "l"(p));
    return a;
}
__device__ __forceinline__ float tf32_hi(float x) {
    uint32_t r;
    asm("cvt.rna.tf32.f32 %0, %1;" : "=r"(r) : "f"(x));
    return __uint_as_float(r);
}
// within-8 K permutation: k -> 2*(k&3) + ((k>>2)&1); pairs (k,k+4) become adjacent
__device__ __forceinline__ int perm8(int c) {
    return (c & ~7) | ((c & 3) << 1) | ((c >> 2) & 1);
}

#define CP_ASYNC16(dst, src) \
    asm volatile("cp.async.cg.shared.global [%0], [%1], 16;" :: "r"(dst), "l"(src) : "memory")
#define CP_COMMIT() asm volatile("cp.async.commit_group;" ::: "memory")
#define CP_WAIT2()  asm volatile("cp.async.wait_group 2;" ::: "memory")

#define MMA_TF32(d, a0, a1, a2, a3, b0, b1) \
    asm volatile("mma.sync.aligned.m16n8k8.row.col.f32.tf32.tf32.f32 " \
        "{%0,%1,%2,%3}, {%4,%5,%6,%7}, {%8,%9}, {%0,%1,%2,%3};" \
        : "+f"((d)[0]), "+f"((d)[1]), "+f"((d)[2]), "+f"((d)[3]) \
        : "r"(a0), "r"(a1), "r"(a2), "r"(a3), "r"(b0), "r"(b1))

enum { MODE_PLAIN = 0, MODE_BIAS = 1, MODE_EXP = 3 };

// ---------------- tf32 mma.sync GEMM ----------------
// C[M x N] (+ per-blockIdx.z batch strides) = A[M x K] * B[N x K]^T, fp32.
// A and B must be stored with the within-8 K permutation (perm8).
// PR=1: C written with perm8 on columns + tf32-RNA rounding (for GEMM-chained scratch).
// MODE_EXP: C = exp(alpha*acc) (exact layout) + fused column sums into colsum.
template <int MODE, int PR>
__global__ void __launch_bounds__(256, 2)
tgemm_k(const float* __restrict__ A, const float* __restrict__ B, float* __restrict__ C,
        int Kn, int lda, int ldb, int ldc,
        long long sA, long long sB, long long sC,
        const float* __restrict__ bias, int sBias, float alpha,
        float* __restrict__ colsum, int sCol)
{
    extern __shared__ float smem[];
    const uint32_t smem_b = smem_u32(smem);
    const int h = blockIdx.z;
    A += (long long)h * sA;
    B += (long long)h * sB;
    C += (long long)h * sC;

    const int t = threadIdx.x;
    const int wid = t >> 5, lane = t & 31;
    const int lr = lane >> 2;    // 0..7
    const int lc = lane & 3;     // 0..3
    const int wm = (wid & 1) * 64;
    const int wn = (wid >> 1) * 32;
    const int row0 = blockIdx.y * BM;
    const int col0 = blockIdx.x * BN;
    const int nKT = Kn / BK;

    const int f_row0 = t >> 2, f_cc0 = t & 3;
    const int f_row1 = (t + 256) >> 2;

#define LOAD_TILE(kt, s) do { \
    long long _k0 = (long long)(kt) * BK; \
    uint32_t _sa = smem_b + (s) * STAGE_FLOATS * 4; \
    uint32_t _sb = _sa + TILE_FLOATS * 4; \
    CP_ASYNC16(_sa + (f_row0 * TPAD + f_cc0 * 4) * 4, A + (long long)(row0 + f_row0) * lda + _k0 + f_cc0 * 4); \
    CP_ASYNC16(_sa + (f_row1 * TPAD + f_cc0 * 4) * 4, A + (long long)(row0 + f_row1) * lda + _k0 + f_cc0 * 4); \
    CP_ASYNC16(_sb + (f_row0 * TPAD + f_cc0 * 4) * 4, B + (long long)(col0 + f_row0) * ldb + _k0 + f_cc0 * 4); \
    CP_ASYNC16(_sb + (f_row1 * TPAD + f_cc0 * 4) * 4, B + (long long)(col0 + f_row1) * ldb + _k0 + f_cc0 * 4); \
} while (0)

    float acc[4][4][4];
#pragma unroll
    for (int i = 0; i < 4; i++)
#pragma unroll
        for (int j = 0; j < 4; j++)
#pragma unroll
            for (int q = 0; q < 4; q++) acc[i][j][q] = 0.0f;

    LOAD_TILE(0, 0); CP_COMMIT();
    LOAD_TILE(1, 1); CP_COMMIT();
    LOAD_TILE(2, 2); CP_COMMIT();

    for (int it = 0; it < nKT; it++) {
        CP_WAIT2();
        __syncthreads();
        if (it + 3 < nKT) LOAD_TILE(it + 3, (it + 3) & 3);
        CP_COMMIT();

        const float* As = smem + (it & 3) * STAGE_FLOATS;
        const float* Bs = As + TILE_FLOATS;
        const float* Ab = As + (wm + lr) * TPAD + 2 * lc;
        const float* Bb = Bs + (wn + lr) * TPAD + 2 * lc;
#pragma unroll
        for (int ks = 0; ks < 2; ks++) {
            const int ko = ks * 8;
            uint2 a[4][2], b[4];
#pragma unroll
            for (int i = 0; i < 4; i++) {
                a[i][0] = *(const uint2*)(Ab + i * 16 * TPAD + ko);
                a[i][1] = *(const uint2*)(Ab + i * 16 * TPAD + 8 * TPAD + ko);
            }
#pragma unroll
            for (int j = 0; j < 4; j++)
                b[j] = *(const uint2*)(Bb + j * 8 * TPAD + ko);
#pragma unroll
            for (int i = 0; i < 4; i++)
#pragma unroll
                for (int j = 0; j < 4; j++)
                    MMA_TF32(acc[i][j], a[i][0].x, a[i][1].x, a[i][0].y, a[i][1].y,
                             b[j].x, b[j].y);
        }
    }

    // epilogue
#pragma unroll
    for (int j = 0; j < 4; j++) {
        const int c = col0 + wn + j * 8 + lc * 2;
        float b0 = 0.0f, b1 = 0.0f;
        if (MODE == MODE_BIAS) {
            b0 = bias[(long long)h * sBias + c];
            b1 = bias[(long long)h * sBias + c + 1];
        }
        float s0 = 0.0f, s1 = 0.0f;
#pragma unroll
        for (int i = 0; i < 4; i++) {
            const int r = row0 + wm + i * 16 + lr;
            float d0 = acc[i][j][0], d1 = acc[i][j][1];
            float d2 = acc[i][j][2], d3 = acc[i][j][3];
            if (MODE == MODE_EXP) {
                d0 = __expf(d0 * alpha); d1 = __expf(d1 * alpha);
                d2 = __expf(d2 * alpha); d3 = __expf(d3 * alpha);
                s0 += d0 + d2; s1 += d1 + d3;
            } else if (MODE == MODE_BIAS) {
                d0 += b0; d1 += b1; d2 += b0; d3 += b1;
            }
            if (PR) {
                const int cp0 = perm8(c), cp1 = perm8(c + 1);
                C[(long long)r * ldc + cp0]       = tf32_hi(d0);
                C[(long long)r * ldc + cp1]       = tf32_hi(d1);
                C[(long long)(r + 8) * ldc + cp0] = tf32_hi(d2);
                C[(long long)(r + 8) * ldc + cp1] = tf32_hi(d3);
            } else {
                *(float2*)&C[(long long)r * ldc + c]       = make_float2(d0, d1);
                *(float2*)&C[(long long)(r + 8) * ldc + c] = make_float2(d2, d3);
            }
        }
        if (MODE == MODE_EXP) {
            // reduce over lr (lane bits 2..4), then lanes 0..3 own column pairs
#pragma unroll
            for (int msk = 4; msk <= 16; msk <<= 1) {
                s0 += __shfl_xor_sync(0xFFFFFFFFu, s0, msk);
                s1 += __shfl_xor_sync(0xFFFFFFFFu, s1, msk);
            }
            if (lane < 4) {
                atomicAdd(&colsum[(long long)h * sCol + c], s0);
                atomicAdd(&colsum[(long long)h * sCol + c + 1], s1);
            }
        }
    }
}

// ---------------- prep / softmax kernels ----------------

// in [R,C] -> out [R,3C] permuted: a_style=1 -> [hi|lo|hi], a_style=0 -> [hi|hi|lo]
__global__ void split3_k(const float* __restrict__ in, float* __restrict__ out,
                         int C, long long total, int a_style) {
    for (long long i = (long long)blockIdx.x * blockDim.x + threadIdx.x;
         i < total; i += (long long)gridDim.x * blockDim.x) {
        long long r = i / C;
        int c = (int)(i - r * C);
        float x = in[i];
        float hi = tf32_hi(x), lo = x - hi;
        float* o = out + r * 3LL * C;
        int cp = perm8(c);
        o[cp] = hi;
        o[C + cp] = a_style ? lo : hi;
        o[2 * C + cp] = a_style ? hi : lo;
    }
}

// W [h][D][E] -> out [h][E][3D] B-style ([hi|hi|lo]), K-permuted
__global__ void split3T_k(const float* __restrict__ in, float* __restrict__ out, int D, int E) {
    __shared__ float tile[32][33];
    const int h = blockIdx.z;
    const int e0 = blockIdx.x * 32, d0 = blockIdx.y * 32;
    in += (size_t)h * D * E;
    out += (size_t)h * E * 3 * D;
    const int x = threadIdx.x, y = threadIdx.y;
#pragma unroll
    for (int j = 0; j < 32; j += 8)
        tile[y + j][x] = in[(long long)(d0 + y + j) * E + e0 + x];
    __syncthreads();
#pragma unroll
    for (int j = 0; j < 32; j += 8) {
        float v = tile[x][y + j];
        float hi = tf32_hi(v), lo = v - hi;
        long long o = (long long)(e0 + y + j) * 3 * D + d0 + perm8(x);
        out[o] = hi;
        out[o + D] = hi;
        out[o + 2 * D] = lo;
    }
}

// in [R,C] -> out [C,R], RNA tf32-rounded, K(out col)-permuted
__global__ void transpose_k(const float* __restrict__ in, float* __restrict__ out,
                            int R, int C) {
    __shared__ float tile[32][33];
    const int c0 = blockIdx.x * 32, r0 = blockIdx.y * 32;
    const int x = threadIdx.x, y = threadIdx.y;
#pragma unroll
    for (int j = 0; j < 32; j += 8)
        tile[y + j][x] = in[(long long)(r0 + y + j) * C + c0 + x];
    __syncthreads();
#pragma unroll
    for (int j = 0; j < 32; j += 8) {
        float v = tile[x][y + j];
        out[(long long)(c0 + y + j) * R + r0 + perm8(x)] = tf32_hi(v);
    }
}

__global__ void zero_colsum_k() {
    int i = blockIdx.x * blockDim.x + threadIdx.x;
    if (i < HEADS * MKNOW) g_colsum[i] = 0.0f;
}

// w[h,n,m] /= colsum[h,m] in place (exact output); also write tf32-rounded,
// K-permuted copy into g_wrnd for the attn GEMM's A operand.
__global__ void normalize_k(float* __restrict__ w, float* __restrict__ wr) {
    const long long total4 = (long long)HEADS * NSENT * MKNOW / 4;
    for (long long i = (long long)blockIdx.x * blockDim.x + threadIdx.x;
         i < total4; i += (long long)gridDim.x * blockDim.x) {
        long long e = i << 2;
        int h = (int)(e >> 24);
        int m = (int)(e & (MKNOW - 1));
        const float* cs = &g_colsum[h * MKNOW + m];
        float4 v = ((float4*)w)[i];
        v.x /= cs[0]; v.y /= cs[1]; v.z /= cs[2]; v.w /= cs[3];
        ((float4*)w)[i] = v;
        // permuted: m..m+3 (m%4==0) -> (m&~7)+((m>>2)&1) + {0,2,4,6}
        long long rowbase = e - m;
        int pb = (m & ~7) + ((m >> 2) & 1);
        wr[rowbase + pb]     = tf32_hi(v.x);
        wr[rowbase + pb + 2] = tf32_hi(v.y);
        wr[rowbase + pb + 4] = tf32_hi(v.z);
        wr[rowbase + pb + 6] = tf32_hi(v.w);
    }
}

// ---------------- launch ----------------
extern "C" void kernel_launch(void* const* d_in, const int* in_sizes, int n_in,
                              void* d_out, int out_size)
{
    const float* sentences = (const float*)d_in[0];
    const float* knowledge = (const float*)d_in[1];
    const float* W_s = (const float*)d_in[2];
    const float* b_s = (const float*)d_in[3];
    const float* W_k = (const float*)d_in[4];
    const float* b_k = (const float*)d_in[5];
    const float* W_f = (const float*)d_in[6];
    const float* b_f = (const float*)d_in[7];

    float* out0 = (float*)d_out;                        // [4096,1024]
    float* wout = out0 + (long long)NSENT * SENTD;      // [8*4096,4096]

    float* gSent3 = nullptr; cudaGetSymbolAddress((void**)&gSent3, g_sent3);
    float* gKnow3 = nullptr; cudaGetSymbolAddress((void**)&gKnow3, g_know3);
    float* gWsT3 = nullptr;  cudaGetSymbolAddress((void**)&gWsT3, g_WsT3);
    float* gWkT3 = nullptr;  cudaGetSymbolAddress((void**)&gWkT3, g_WkT3);
    float* gS = nullptr;     cudaGetSymbolAddress((void**)&gS, g_S);
    float* gKp = nullptr;    cudaGetSymbolAddress((void**)&gKp, g_Kp);
    float* gS3 = nullptr;    cudaGetSymbolAddress((void**)&gS3, g_S3);
    float* gKp3 = nullptr;   cudaGetSymbolAddress((void**)&gKp3, g_Kp3);
    float* gKnT = nullptr;   cudaGetSymbolAddress((void**)&gKnT, g_knowT);
    float* gWfT = nullptr;   cudaGetSymbolAddress((void**)&gWfT, g_WfT);
    float* gCc = nullptr;    cudaGetSymbolAddress((void**)&gCc, g_concat);
    float* gWr = nullptr;    cudaGetSymbolAddress((void**)&gWr, g_wrnd);
    float* gCs = nullptr;    cudaGetSymbolAddress((void**)&gCs, g_colsum);

    cudaFuncSetAttribute(tgemm_k<MODE_BIAS, 0>,  cudaFuncAttributeMaxDynamicSharedMemorySize, SMEM_BYTES);
    cudaFuncSetAttribute(tgemm_k<MODE_EXP, 0>,   cudaFuncAttributeMaxDynamicSharedMemorySize, SMEM_BYTES);
    cudaFuncSetAttribute(tgemm_k<MODE_PLAIN, 1>, cudaFuncAttributeMaxDynamicSharedMemorySize, SMEM_BYTES);

    const float inv_sqrt_hd = 0.08838834764831845f;

    // --- prep: tf32 splits + transposes (all K-permuted) ---
    split3_k<<<1024, 256>>>(sentences, gSent3, SENTD, (long long)NSENT * SENTD, 1);
    split3_k<<<1024, 256>>>(knowledge, gKnow3, SENTD, (long long)MKNOW * SENTD, 1);
    split3T_k<<<dim3(HD / 32, SENTD / 32, HEADS), dim3(32, 8)>>>(W_s, gWsT3, SENTD, HD);
    split3T_k<<<dim3(HD / 32, SENTD / 32, HEADS), dim3(32, 8)>>>(W_k, gWkT3, SENTD, HD);
    transpose_k<<<dim3(SENTD / 32, MKNOW / 32), dim3(32, 8)>>>(knowledge, gKnT, MKNOW, SENTD);
    transpose_k<<<dim3(SENTD / 32, (HEADS * SENTD) / 32), dim3(32, 8)>>>(W_f, gWfT, HEADS * SENTD, SENTD);
    zero_colsum_k<<<(HEADS * MKNOW + 255) / 256, 256>>>();

    // --- projections (split tf32, K=3072) ---
    tgemm_k<MODE_BIAS, 0><<<dim3(1, NSENT / BM, HEADS), 256, SMEM_BYTES>>>(
        gSent3, gWsT3, gS, 3 * SENTD, 3 * SENTD, 3 * SENTD, HD,
        0LL, (long long)HD * 3 * SENTD, (long long)NSENT * HD, b_s, HD, 0.0f, nullptr, 0);
    tgemm_k<MODE_BIAS, 0><<<dim3(1, MKNOW / BM, HEADS), 256, SMEM_BYTES>>>(
        gKnow3, gWkT3, gKp, 3 * SENTD, 3 * SENTD, 3 * SENTD, HD,
        0LL, (long long)HD * 3 * SENTD, (long long)MKNOW * HD, b_k, HD, 0.0f, nullptr, 0);

    // --- split S/Kp for the scores GEMM ---
    split3_k<<<1024, 256>>>(gS, gS3, HD, (long long)HEADS * NSENT * HD, 1);
    split3_k<<<1024, 256>>>(gKp, gKp3, HD, (long long)HEADS * MKNOW * HD, 0);

    // --- scores (split tf32, K=384) -> exp -> weights output; fused column sums ---
    tgemm_k<MODE_EXP, 0><<<dim3(MKNOW / BN, NSENT / BM, HEADS), 256, SMEM_BYTES>>>(
        gS3, gKp3, wout, 3 * HD, 3 * HD, 3 * HD, MKNOW,
        (long long)NSENT * 3 * HD, (long long)MKNOW * 3 * HD, (long long)NSENT * MKNOW,
        nullptr, 0, inv_sqrt_hd, gCs, MKNOW);

    // --- softmax normalize (exact) + rounded/permuted copy for attn ---
    normalize_k<<<4096, 256>>>(wout, gWr);

    // --- attn: wrnd[h] @ knowT^T -> concat (rounded+permuted for final GEMM) ---
    tgemm_k<MODE_PLAIN, 1><<<dim3(SENTD / BN, NSENT / BM, HEADS), 256, SMEM_BYTES>>>(
        gWr, gKnT, gCc, MKNOW, MKNOW, MKNOW, HEADS * SENTD,
        (long long)NSENT * MKNOW, 0LL, (long long)SENTD, nullptr, 0, 0.0f, nullptr, 0);

    // --- final: concat @ W_f + b_f (K=8192) ---
    tgemm_k<MODE_BIAS, 0><<<dim3(SENTD / BN, NSENT / BM, 1), 256, SMEM_BYTES>>>(
        gCc, gWfT, out0, HEADS * SENTD, HEADS * SENTD, HEADS * SENTD, SENTD,
        0LL, 0LL, 0LL, b_f, 0, 0.0f, nullptr, 0);
}

// round 6
// speedup vs baseline: 5.1469x; 1.9621x over previous
#include <cuda_runtime.h>
#include <cuda_fp16.h>
#include <cstdint>
#include <math.h>

// ---------------- problem constants ----------------
#define NSENT 4096
#define MKNOW 4096
#define HEADS 8
#define SENTD 1024
#define HD    128

// ---------------- GEMM tile config ----------------
#define BM 128
#define BN 128
#define BKH 32                          // k halves per stage (2 mma k16 steps)
#define TILE_BYTES_H (128 * 64)         // 128 rows x 64B
#define STAGE_BYTES (2 * TILE_BYTES_H)  // A + B = 16 KB
#define STAGES 4
#define SMEM_BYTES (STAGES * STAGE_BYTES)   // 64 KB -> 2 CTAs/SM

// ---------------- scratch (static device arrays) ----------------
__device__ __half g_sent3h[(size_t)NSENT*3*SENTD];
__device__ __half g_know3h[(size_t)MKNOW*3*SENTD];
__device__ __half g_WsT3h[(size_t)HEADS*HD*3*SENTD];
__device__ __half g_WkT3h[(size_t)HEADS*HD*3*SENTD];
__device__ float  g_S  [(size_t)HEADS*NSENT*HD];
__device__ float  g_Kp [(size_t)HEADS*MKNOW*HD];
__device__ __half g_S3h [(size_t)HEADS*NSENT*3*HD];
__device__ __half g_Kp3h[(size_t)HEADS*MKNOW*3*HD];
__device__ __half g_knowTh[(size_t)SENTD*MKNOW];
__device__ __half g_WfTh[(size_t)SENTD*HEADS*SENTD];
__device__ __half g_concath[(size_t)NSENT*HEADS*SENTD];
__device__ __half g_wrndh[(size_t)HEADS*NSENT*MKNOW];
__device__ float  g_colsum[HEADS*MKNOW];

// ---------------- helpers ----------------
__device__ __forceinline__ uint32_t smem_u32(const void* p) {
    uint32_t a;
    asm("{ .reg .u64 t; cvta.to.shared.u64 t, %1; cvt.u32.u64 %0, t; }" : "=r"(a) : "l"(p));
    return a;
}
// within-16 K permutation: k = 8b + 2c + r  ->  4c + 2b + r
__device__ __forceinline__ int perm16(int k) {
    return (k & ~15) | (((k >> 1) & 3) << 2) | (((k >> 3) & 1) << 1) | (k & 1);
}

#define CP_ASYNC16(dst, src) \
    asm volatile("cp.async.cg.shared.global [%0], [%1], 16;" :: "r"(dst), "l"(src) : "memory")
#define CP_COMMIT() asm volatile("cp.async.commit_group;" ::: "memory")
#define CP_WAIT2()  asm volatile("cp.async.wait_group 2;" ::: "memory")

#define MMA_F16(d, a0, a1, a2, a3, b0, b1) \
    asm volatile("mma.sync.aligned.m16n8k16.row.col.f32.f16.f16.f32 " \
        "{%0,%1,%2,%3}, {%4,%5,%6,%7}, {%8,%9}, {%0,%1,%2,%3};" \
        : "+f"((d)[0]), "+f"((d)[1]), "+f"((d)[2]), "+f"((d)[3]) \
        : "r"(a0), "r"(a1), "r"(a2), "r"(a3), "r"(b0), "r"(b1))

enum { MODE_PLAIN = 0, MODE_BIAS = 1, MODE_EXP = 3 };

// ---------------- fp16 mma.sync GEMM ----------------
// C[M x N] (+ per-blockIdx.z batch strides) = A[M x K] * B[N x K]^T.
// A, B: __half, stored with the within-16 K permutation (perm16).
// PR=0: C fp32 (optional bias / exp+colsum). PR=1: C __half, columns perm16'd
// and RN-rounded (scratch feeding another GEMM).
template <int MODE, int PR>
__global__ void __launch_bounds__(256, 2)
hgemm_k(const __half* __restrict__ A, const __half* __restrict__ B, void* __restrict__ Cv,
        int Kn, int lda, int ldb, int ldc,
        long long sA, long long sB, long long sC,
        const float* __restrict__ bias, int sBias, float alpha,
        float* __restrict__ colsum, int sCol)
{
    extern __shared__ char smem[];
    const uint32_t smem_b = smem_u32(smem);
    const int h = blockIdx.z;
    A += (long long)h * sA;
    B += (long long)h * sB;

    const int t = threadIdx.x;
    const int wid = t >> 5, lane = t & 31;
    const int lr = lane >> 2;    // 0..7
    const int lc = lane & 3;     // 0..3
    const int wm = (wid & 1) * 64;
    const int wn = (wid >> 1) * 32;
    const int row0 = blockIdx.y * BM;
    const int col0 = blockIdx.x * BN;
    const int nKT = Kn / BKH;

    // cp.async fill: each tile = 128 rows x 64B = 512 x 16B chunks; 2 chunks/thread/tile
    const int fr0 = t >> 2, fo = t & 3;
    const int fr1 = (t + 256) >> 2;
    const uint32_t fd0 = (uint32_t)(fo * 16) ^ ((fr0 & 2) << 4);
    const uint32_t fd1 = (uint32_t)(fo * 16) ^ ((fr1 & 2) << 4);

#define LOAD_TILE(kt, s) do { \
    long long _k0 = (long long)(kt) * BKH; \
    uint32_t _sa = smem_b + (s) * STAGE_BYTES; \
    uint32_t _sb = _sa + TILE_BYTES_H; \
    CP_ASYNC16(_sa + fr0 * 64 + fd0, A + (long long)(row0 + fr0) * lda + _k0 + fo * 8); \
    CP_ASYNC16(_sa + fr1 * 64 + fd1, A + (long long)(row0 + fr1) * lda + _k0 + fo * 8); \
    CP_ASYNC16(_sb + fr0 * 64 + fd0, B + (long long)(col0 + fr0) * ldb + _k0 + fo * 8); \
    CP_ASYNC16(_sb + fr1 * 64 + fd1, B + (long long)(col0 + fr1) * ldb + _k0 + fo * 8); \
} while (0)

    float acc[4][4][4];
#pragma unroll
    for (int i = 0; i < 4; i++)
#pragma unroll
        for (int j = 0; j < 4; j++)
#pragma unroll
            for (int q = 0; q < 4; q++) acc[i][j][q] = 0.0f;

    LOAD_TILE(0, 0); CP_COMMIT();
    LOAD_TILE(1, 1); CP_COMMIT();
    LOAD_TILE(2, 2); CP_COMMIT();

    // per-thread swizzle term for fragment loads ((row&2) is lr&2 for all rows used)
    const uint32_t swz = (uint32_t)((lr & 2) << 4);

    for (int it = 0; it < nKT; it++) {
        CP_WAIT2();
        __syncthreads();
        if (it + 3 < nKT) LOAD_TILE(it + 3, (it + 3) & 3);
        CP_COMMIT();

        const char* As = smem + (it & 3) * STAGE_BYTES;
        const char* Bs = As + TILE_BYTES_H;
#pragma unroll
        for (int ks = 0; ks < 2; ks++) {
            const uint32_t koff = (uint32_t)(lc * 8) + (((uint32_t)ks << 5) ^ swz);
            uint2 al[4], ah[4], b[4];
#pragma unroll
            for (int i = 0; i < 4; i++) {
                const int ra = wm + i * 16 + lr;
                al[i] = *(const uint2*)(As + ra * 64 + koff);
                ah[i] = *(const uint2*)(As + (ra + 8) * 64 + koff);
            }
#pragma unroll
            for (int j = 0; j < 4; j++) {
                const int rb = wn + j * 8 + lr;
                b[j] = *(const uint2*)(Bs + rb * 64 + koff);
            }
#pragma unroll
            for (int i = 0; i < 4; i++)
#pragma unroll
                for (int j = 0; j < 4; j++)
                    MMA_F16(acc[i][j], al[i].x, ah[i].x, al[i].y, ah[i].y, b[j].x, b[j].y);
        }
    }

    // epilogue
    float* Cf = (float*)Cv + (PR ? 0 : (long long)h * sC);
    __half* Ch = (__half*)Cv + (PR ? (long long)h * sC : 0);
#pragma unroll
    for (int j = 0; j < 4; j++) {
        const int c = col0 + wn + j * 8 + lc * 2;
        float b0 = 0.0f, b1 = 0.0f;
        if (MODE == MODE_BIAS) {
            b0 = bias[(long long)h * sBias + c];
            b1 = bias[(long long)h * sBias + c + 1];
        }
        float s0 = 0.0f, s1 = 0.0f;
#pragma unroll
        for (int i = 0; i < 4; i++) {
            const int r = row0 + wm + i * 16 + lr;
            float d0 = acc[i][j][0], d1 = acc[i][j][1];
            float d2 = acc[i][j][2], d3 = acc[i][j][3];
            if (MODE == MODE_EXP) {
                d0 = __expf(d0 * alpha); d1 = __expf(d1 * alpha);
                d2 = __expf(d2 * alpha); d3 = __expf(d3 * alpha);
                s0 += d0 + d2; s1 += d1 + d3;
            } else if (MODE == MODE_BIAS) {
                d0 += b0; d1 += b1; d2 += b0; d3 += b1;
            }
            if (PR) {
                const int pc = perm16(c);   // c even -> perm16(c+1) == pc+1
                *(__half2*)&Ch[(long long)r * ldc + pc] =
                    __floats2half2_rn(d0, d1);
                *(__half2*)&Ch[(long long)(r + 8) * ldc + pc] =
                    __floats2half2_rn(d2, d3);
            } else {
                *(float2*)&Cf[(long long)r * ldc + c]       = make_float2(d0, d1);
                *(float2*)&Cf[(long long)(r + 8) * ldc + c] = make_float2(d2, d3);
            }
        }
        if (MODE == MODE_EXP) {
#pragma unroll
            for (int msk = 4; msk <= 16; msk <<= 1) {
                s0 += __shfl_xor_sync(0xFFFFFFFFu, s0, msk);
                s1 += __shfl_xor_sync(0xFFFFFFFFu, s1, msk);
            }
            if (lane < 4) {
                atomicAdd(&colsum[(long long)h * sCol + c], s0);
                atomicAdd(&colsum[(long long)h * sCol + c + 1], s1);
            }
        }
    }
}

// ---------------- prep / softmax kernels ----------------

// fp32 [R,C] -> half [R,3C] perm16'd: a_style=1 -> [hi|lo|hi], 0 -> [hi|hi|lo]
__global__ void split3h_k(const float* __restrict__ in, __half* __restrict__ out,
                          int C, long long total, int a_style) {
    for (long long i = (long long)blockIdx.x * blockDim.x + threadIdx.x;
         i < total; i += (long long)gridDim.x * blockDim.x) {
        long long r = i / C;
        int c = (int)(i - r * C);
        float x = in[i];
        __half hi = __float2half_rn(x);
        __half lo = __float2half_rn(x - __half2float(hi));
        __half* o = out + r * 3LL * C;
        int cp = perm16(c);
        o[cp] = hi;
        o[C + cp] = a_style ? lo : hi;
        o[2 * C + cp] = a_style ? hi : lo;
    }
}

// W [h][D][E] -> half out [h][E][3D] B-style ([hi|hi|lo]), perm16'd
__global__ void split3Th_k(const float* __restrict__ in, __half* __restrict__ out,
                           int D, int E) {
    __shared__ float tile[32][33];
    const int h = blockIdx.z;
    const int e0 = blockIdx.x * 32, d0 = blockIdx.y * 32;
    in += (size_t)h * D * E;
    out += (size_t)h * E * 3 * D;
    const int x = threadIdx.x, y = threadIdx.y;
#pragma unroll
    for (int j = 0; j < 32; j += 8)
        tile[y + j][x] = in[(long long)(d0 + y + j) * E + e0 + x];
    __syncthreads();
#pragma unroll
    for (int j = 0; j < 32; j += 8) {
        float v = tile[x][y + j];
        __half hi = __float2half_rn(v);
        __half lo = __float2half_rn(v - __half2float(hi));
        long long o = (long long)(e0 + y + j) * 3 * D + d0 + perm16(x);
        out[o] = hi;
        out[o + D] = hi;
        out[o + 2 * D] = lo;
    }
}

// fp32 [R,C] -> half [C,R] RN-rounded, out-col perm16'd
__global__ void transposeh_k(const float* __restrict__ in, __half* __restrict__ out,
                             int R, int C) {
    __shared__ float tile[32][33];
    const int c0 = blockIdx.x * 32, r0 = blockIdx.y * 32;
    const int x = threadIdx.x, y = threadIdx.y;
#pragma unroll
    for (int j = 0; j < 32; j += 8)
        tile[y + j][x] = in[(long long)(r0 + y + j) * C + c0 + x];
    __syncthreads();
#pragma unroll
    for (int j = 0; j < 32; j += 8)
        out[(long long)(c0 + y + j) * R + r0 + perm16(x)] =
            __float2half_rn(tile[x][y + j]);
}

__global__ void zero_colsum_k() {
    int i = blockIdx.x * blockDim.x + threadIdx.x;
    if (i < HEADS * MKNOW) g_colsum[i] = 0.0f;
}

// w[h,n,m] /= colsum[h,m] in place (exact fp32 output); also write RN-rounded,
// perm16'd half copy for the attn GEMM's A operand.
__global__ void normalize_k(float* __restrict__ w, __half* __restrict__ wr) {
    const long long total4 = (long long)HEADS * NSENT * MKNOW / 4;
    for (long long i = (long long)blockIdx.x * blockDim.x + threadIdx.x;
         i < total4; i += (long long)gridDim.x * blockDim.x) {
        long long e = i << 2;
        int h = (int)(e >> 24);
        int m = (int)(e & (MKNOW - 1));
        const float* cs = &g_colsum[h * MKNOW + m];
        float4 v = ((float4*)w)[i];
        v.x /= cs[0]; v.y /= cs[1]; v.z /= cs[2]; v.w /= cs[3];
        ((float4*)w)[i] = v;
        long long rowbase = e - m;
        wr[rowbase + perm16(m)]     = __float2half_rn(v.x);
        wr[rowbase + perm16(m + 1)] = __float2half_rn(v.y);
        wr[rowbase + perm16(m + 2)] = __float2half_rn(v.z);
        wr[rowbase + perm16(m + 3)] = __float2half_rn(v.w);
    }
}

// ---------------- launch ----------------
extern "C" void kernel_launch(void* const* d_in, const int* in_sizes, int n_in,
                              void* d_out, int out_size)
{
    const float* sentences = (const float*)d_in[0];
    const float* knowledge = (const float*)d_in[1];
    const float* W_s = (const float*)d_in[2];
    const float* b_s = (const float*)d_in[3];
    const float* W_k = (const float*)d_in[4];
    const float* b_k = (const float*)d_in[5];
    const float* W_f = (const float*)d_in[6];
    const float* b_f = (const float*)d_in[7];

    float* out0 = (float*)d_out;                        // [4096,1024]
    float* wout = out0 + (long long)NSENT * SENTD;      // [8*4096,4096]

    __half* gSent3 = nullptr; cudaGetSymbolAddress((void**)&gSent3, g_sent3h);
    __half* gKnow3 = nullptr; cudaGetSymbolAddress((void**)&gKnow3, g_know3h);
    __half* gWsT3 = nullptr;  cudaGetSymbolAddress((void**)&gWsT3, g_WsT3h);
    __half* gWkT3 = nullptr;  cudaGetSymbolAddress((void**)&gWkT3, g_WkT3h);
    float* gS = nullptr;      cudaGetSymbolAddress((void**)&gS, g_S);
    float* gKp = nullptr;     cudaGetSymbolAddress((void**)&gKp, g_Kp);
    __half* gS3 = nullptr;    cudaGetSymbolAddress((void**)&gS3, g_S3h);
    __half* gKp3 = nullptr;   cudaGetSymbolAddress((void**)&gKp3, g_Kp3h);
    __half* gKnT = nullptr;   cudaGetSymbolAddress((void**)&gKnT, g_knowTh);
    __half* gWfT = nullptr;   cudaGetSymbolAddress((void**)&gWfT, g_WfTh);
    __half* gCc = nullptr;    cudaGetSymbolAddress((void**)&gCc, g_concath);
    __half* gWr = nullptr;    cudaGetSymbolAddress((void**)&gWr, g_wrndh);
    float* gCs = nullptr;     cudaGetSymbolAddress((void**)&gCs, g_colsum);

    cudaFuncSetAttribute(hgemm_k<MODE_BIAS, 0>,  cudaFuncAttributeMaxDynamicSharedMemorySize, SMEM_BYTES);
    cudaFuncSetAttribute(hgemm_k<MODE_EXP, 0>,   cudaFuncAttributeMaxDynamicSharedMemorySize, SMEM_BYTES);
    cudaFuncSetAttribute(hgemm_k<MODE_PLAIN, 1>, cudaFuncAttributeMaxDynamicSharedMemorySize, SMEM_BYTES);

    const float inv_sqrt_hd = 0.08838834764831845f;

    // --- prep: fp16 splits + transposes (all K-perm16'd) ---
    split3h_k<<<1024, 256>>>(sentences, gSent3, SENTD, (long long)NSENT * SENTD, 1);
    split3h_k<<<1024, 256>>>(knowledge, gKnow3, SENTD, (long long)MKNOW * SENTD, 1);
    split3Th_k<<<dim3(HD / 32, SENTD / 32, HEADS), dim3(32, 8)>>>(W_s, gWsT3, SENTD, HD);
    split3Th_k<<<dim3(HD / 32, SENTD / 32, HEADS), dim3(32, 8)>>>(W_k, gWkT3, SENTD, HD);
    transposeh_k<<<dim3(SENTD / 32, MKNOW / 32), dim3(32, 8)>>>(knowledge, gKnT, MKNOW, SENTD);
    transposeh_k<<<dim3(SENTD / 32, (HEADS * SENTD) / 32), dim3(32, 8)>>>(W_f, gWfT, HEADS * SENTD, SENTD);
    zero_colsum_k<<<(HEADS * MKNOW + 255) / 256, 256>>>();

    // --- projections (split fp16, K=3072) -> fp32 S / Kp ---
    hgemm_k<MODE_BIAS, 0><<<dim3(1, NSENT / BM, HEADS), 256, SMEM_BYTES>>>(
        gSent3, gWsT3, gS, 3 * SENTD, 3 * SENTD, 3 * SENTD, HD,
        0LL, (long long)HD * 3 * SENTD, (long long)NSENT * HD, b_s, HD, 0.0f, nullptr, 0);
    hgemm_k<MODE_BIAS, 0><<<dim3(1, MKNOW / BM, HEADS), 256, SMEM_BYTES>>>(
        gKnow3, gWkT3, gKp, 3 * SENTD, 3 * SENTD, 3 * SENTD, HD,
        0LL, (long long)HD * 3 * SENTD, (long long)MKNOW * HD, b_k, HD, 0.0f, nullptr, 0);

    // --- split S/Kp (fp16) for the scores GEMM ---
    split3h_k<<<1024, 256>>>(gS, gS3, HD, (long long)HEADS * NSENT * HD, 1);
    split3h_k<<<1024, 256>>>(gKp, gKp3, HD, (long long)HEADS * MKNOW * HD, 0);

    // --- scores (split fp16, K=384) -> exp -> weights output; fused column sums ---
    hgemm_k<MODE_EXP, 0><<<dim3(MKNOW / BN, NSENT / BM, HEADS), 256, SMEM_BYTES>>>(
        gS3, gKp3, wout, 3 * HD, 3 * HD, 3 * HD, MKNOW,
        (long long)NSENT * 3 * HD, (long long)MKNOW * 3 * HD, (long long)NSENT * MKNOW,
        nullptr, 0, inv_sqrt_hd, gCs, MKNOW);

    // --- softmax normalize (exact fp32) + rounded/perm16'd half copy ---
    normalize_k<<<4096, 256>>>(wout, gWr);

    // --- attn: wrnd[h] @ knowT^T -> concat half (perm16'd cols for final GEMM) ---
    hgemm_k<MODE_PLAIN, 1><<<dim3(SENTD / BN, NSENT / BM, HEADS), 256, SMEM_BYTES>>>(
        gWr, gKnT, gCc, MKNOW, MKNOW, MKNOW, HEADS * SENTD,
        (long long)NSENT * MKNOW, 0LL, (long long)SENTD, nullptr, 0, 0.0f, nullptr, 0);

    // --- final: concat @ W_f + b_f (fp16, K=8192) -> fp32 out ---
    hgemm_k<MODE_BIAS, 0><<<dim3(SENTD / BN, NSENT / BM, 1), 256, SMEM_BYTES>>>(
        gCc, gWfT, out0, HEADS * SENTD, HEADS * SENTD, HEADS * SENTD, SENTD,
        0LL, 0LL, 0LL, b_f, 0, 0.0f, nullptr, 0);
}